// round 10
// baseline (speedup 1.0000x reference)
#include <cuda_runtime.h>
#include <cstdint>

#define TT   1000
#define TM1  999
#define BB   64

// ---------------- constants computed by setup kernel ----------------
__device__ float g_tau[256], g_lam[256], g_AtL[256], g_AtLA[256];
__device__ float g_tau_mu[16], g_AtLb[16], g_Lb[16];
__device__ float g_consts[2];          // [0]=trans_const, [1]=init_const
__device__ unsigned g_keys[BB][2];

// ---------------- scratch (device globals; no allocation) ----------------
__device__ float g_scr1[(size_t)BB * TM1 * 256]; // forward: M^{-1}   -> backward: K^T
__device__ float g_scr2[(size_t)BB * TM1 * 256]; // forward: G=M^{-1}A^tL -> backward: Ls
__device__ float g_scr3[(size_t)BB * TM1 * 16];  // forward: Mim     -> backward: m_t
__device__ float g_eps [(size_t)BB * TT  * 16];  // normal samples

// ---------------- Threefry-2x32 (20 rounds), JAX-compatible ----------------
__device__ __forceinline__ void tf2x32(unsigned k0, unsigned k1,
                                       unsigned x0, unsigned x1,
                                       unsigned &o0, unsigned &o1) {
    unsigned ks2 = k0 ^ k1 ^ 0x1BD11BDAu;
    x0 += k0; x1 += k1;
#define TFR(r) { x0 += x1; x1 = (x1 << (r)) | (x1 >> (32 - (r))); x1 ^= x0; }
    TFR(13) TFR(15) TFR(26) TFR(6)
    x0 += k1;  x1 += ks2 + 1u;
    TFR(17) TFR(29) TFR(16) TFR(24)
    x0 += ks2; x1 += k0 + 2u;
    TFR(13) TFR(15) TFR(26) TFR(6)
    x0 += k0;  x1 += k1 + 3u;
    TFR(17) TFR(29) TFR(16) TFR(24)
    x0 += k1;  x1 += ks2 + 4u;
    TFR(13) TFR(15) TFR(26) TFR(6)
    x0 += ks2; x1 += k0 + 5u;
#undef TFR
    o0 = x0; o1 = x1;
}

// ---------------- block-cooperative Gauss-Jordan on [16 | 16] augmented ----
// all 256 threads must call; returns sum(log(pivots)) if WantLogdet
template <bool WantLogdet>
__device__ __forceinline__ float gj16(float MA[16][33], int i, int j) {
    float logdet = 0.f;
    for (int k = 0; k < 16; ++k) {
        float piv  = MA[k][k];
        float pinv = __fdiv_rn(1.f, piv);
        if (WantLogdet) logdet += logf(piv);
        float aik  = MA[i][k];
        float pkj  = MA[k][j];
        float pkj2 = MA[k][j + 16];
        float aij  = MA[i][j];
        float aij2 = MA[i][j + 16];
        __syncthreads();
        if (i == k) {
            MA[i][j]      = pkj  * pinv;
            MA[i][j + 16] = pkj2 * pinv;
        } else {
            MA[i][j]      = fmaf(-aik, pkj  * pinv, aij);
            MA[i][j + 16] = fmaf(-aik, pkj2 * pinv, aij2);
        }
        __syncthreads();
    }
    return logdet;
}

// ---------------- block-cooperative Cholesky (lower), in place ----------------
__device__ __forceinline__ void chol16(float CH[16][17], int i, int j) {
    for (int k = 0; k < 16; ++k) {
        float dk  = CH[k][k];
        float s   = __fsqrt_rn(dk);
        float inv = __fdiv_rn(1.f, s);
        float aik = CH[i][k];
        float ajk = CH[j][k];
        float cur = CH[i][j];
        __syncthreads();
        if (j == k) {
            if (i >= k) CH[i][k] = aik * inv;
        } else if (j > k && i >= j) {
            CH[i][j] = fmaf(-(aik * inv), (ajk * inv), cur);
        }
        __syncthreads();
    }
}

// ---------------- setup: shared model constants + batch keys ----------------
__device__ float logdet16_local(const float M[16][17]) {
    float a[16][16];
    for (int r = 0; r < 16; ++r)
        for (int c = 0; c < 16; ++c) a[r][c] = M[r][c];
    float ld = 0.f;
    for (int k = 0; k < 16; ++k) {
        float p = a[k][k];
        ld += logf(p);
        float pi_ = __fdiv_rn(1.f, p);
        for (int r = k + 1; r < 16; ++r) {
            float f = a[r][k] * pi_;
            for (int c = k + 1; c < 16; ++c) a[r][c] = fmaf(-f, a[k][c], a[r][c]);
        }
    }
    return ld;
}

__global__ void __launch_bounds__(256) setup_kernel(const float* __restrict__ loc,
                                                    const float* __restrict__ Tau_p,
                                                    const float* __restrict__ Lam_p,
                                                    const float* __restrict__ X) {
    __shared__ float sTau[16][17], sLamS[16][17], sA[16][17], sAtLs[16][17];
    __shared__ float sbv[16], slocv[16];
    int tid = threadIdx.x, i = tid >> 4, j = tid & 15;

    float t = 0.f, l = 0.f;
#pragma unroll
    for (int k = 0; k < 16; ++k) {
        t = fmaf(Tau_p[i * 16 + k], Tau_p[j * 16 + k], t);
        l = fmaf(Lam_p[i * 16 + k], Lam_p[j * 16 + k], l);
    }
    if (i == j) { t += 1e-8f; l += 1e-8f; }
    sTau[i][j] = t; sLamS[i][j] = l;
    sA[i][j]   = X[i * 17 + j];
    if (tid < 16) { sbv[tid] = X[tid * 17 + 16]; slocv[tid] = loc[tid]; }
    __syncthreads();

    float atl = 0.f;
#pragma unroll
    for (int k = 0; k < 16; ++k) atl = fmaf(sA[k][i], sLamS[k][j], atl);
    sAtLs[i][j] = atl;
    __syncthreads();

    float atla = 0.f;
#pragma unroll
    for (int k = 0; k < 16; ++k) atla = fmaf(sAtLs[i][k], sA[k][j], atla);

    g_tau[tid] = t; g_lam[tid] = l; g_AtL[tid] = atl; g_AtLA[tid] = atla;

    if (tid < 16) {
        float tm = 0.f, alb = 0.f, lb = 0.f;
#pragma unroll
        for (int k = 0; k < 16; ++k) {
            tm  = fmaf(sTau[tid][k],  slocv[k], tm);
            alb = fmaf(sAtLs[tid][k], sbv[k],   alb);
            lb  = fmaf(sLamS[tid][k], sbv[k],   lb);
        }
        g_tau_mu[tid] = tm; g_AtLb[tid] = alb; g_Lb[tid] = lb;
    }
    // batch keys: foldlike split of key (0,42): key_b = threefry((0,42), (0,b))
    if (tid < BB) {
        unsigned o0, o1;
        tf2x32(0u, 42u, 0u, (unsigned)tid, o0, o1);
        g_keys[tid][0] = o0; g_keys[tid][1] = o1;
    }
    __syncthreads();
    if (tid == 0) {
        float ldl = logdet16_local(sLamS);
        float ldt = logdet16_local(sTau);
        float bLb = 0.f, ltm = 0.f;
        for (int k = 0; k < 16; ++k) {
            bLb = fmaf(sbv[k],   g_Lb[k],     bLb);
            ltm = fmaf(slocv[k], g_tau_mu[k], ltm);
        }
        g_consts[0] = -0.5f * bLb + 0.5f * ldl;  // trans_const
        g_consts[1] = -0.5f * ltm + 0.5f * ldt;  // init_const
    }
}

// ---------------- main: per-batch forward / backward / sample ----------------
__global__ void __launch_bounds__(256, 1) lds_main(const float* __restrict__ Jr,
                                                   const float* __restrict__ hr,
                                                   float* __restrict__ out) {
    const int b   = blockIdx.x;
    const int tid = threadIdx.x;
    const int i   = tid >> 4, j = tid & 15;

    const float trans_const = g_consts[0];
    const float init_const  = g_consts[1];

    const float* Jb = Jr + (size_t)b * TT * 16;
    const float* Hb = hr + (size_t)b * TT * 16;
    float* scr1 = g_scr1 + (size_t)b * TM1 * 256;
    float* scr2 = g_scr2 + (size_t)b * TM1 * 256;
    float* scr3 = g_scr3 + (size_t)b * TM1 * 16;
    float* epsb = g_eps  + (size_t)b * TT * 16;

    // output layout: z | kl | EXXT | EX | EXXNT (tuple order, flattened)
    const size_t KL_OFF    = (size_t)BB * TT * 16;
    const size_t EXXT_OFF  = KL_OFF + BB;
    const size_t EX_OFF    = EXXT_OFF + (size_t)BB * TT * 256;
    const size_t EXXNT_OFF = EX_OFF + (size_t)BB * TT * 16;
    float* zO     = out + (size_t)b * TT * 16;
    float* exxtO  = out + EXXT_OFF + (size_t)b * TT * 256;
    float* exO    = out + EX_OFF + (size_t)b * TT * 16;
    float* exxntO = out + EXXNT_OFF + (size_t)b * TM1 * 256;

    __shared__ float sAtL[16][17], sAtLA[16][17], sLam[16][17];
    __shared__ float sAtLb[16], sLb[16];
    __shared__ float MA[16][33];
    __shared__ float PiG[16][17];  // fJ (fwd) / Pi (bwd) / K^T (sample)
    __shared__ float Gm[16][17];   // G (fwd,bwd) / Ls (sample)
    __shared__ float Wb[16][17];
    __shared__ float Vn[16][17], Vt[16][17];
    __shared__ float CH[16][17];
    __shared__ float fh[16], mvec[16], Mimv[16], mn[16], mt[16], mT_s[16];
    __shared__ float nxtJ[16], nxtH[16];
    __shared__ float xc[16], xn[16], sE[16];

    // ---- epsilon generation (partitionable random_bits: lane0 ^ lane1) ----
    {
        unsigned k0 = g_keys[b][0], k1 = g_keys[b][1];
        for (int idx = tid; idx < TT * 16; idx += 256) {
            unsigned o0, o1;
            tf2x32(k0, k1, 0u, (unsigned)idx, o0, o1);
            unsigned bits = o0 ^ o1;
            float f = __uint_as_float((bits >> 9) | 0x3f800000u) - 1.0f;
            const float lo = -0.99999994f;           // nextafter(-1, 0)
            float v = fmaxf(lo, f * 2.0f + lo);
            epsb[idx] = 1.4142135623730951f * erfinvf(v);
        }
    }

    // ---- constants + initial carry ----
    sAtL[i][j]  = g_AtL[tid];
    sAtLA[i][j] = g_AtLA[tid];
    sLam[i][j]  = g_lam[tid];
    PiG[i][j]   = g_tau[tid] + ((i == j) ? (Jb[i] + 0.5f) : 0.f);  // fJ0
    if (tid < 16) {
        sAtLb[tid] = g_AtLb[tid];
        sLb[tid]   = g_Lb[tid];
        fh[tid]    = g_tau_mu[tid] + Hb[tid];
    }
    __syncthreads();

    float lz = 0.f, klacc = 0.f;

    // ======================= FORWARD FILTER =======================
    for (int t = 0; t < TM1; ++t) {
        MA[i][j]      = PiG[i][j] + sAtLA[i][j];
        MA[i][j + 16] = (i == j) ? 1.f : 0.f;
        if (tid < 16) {
            mvec[tid] = fh[tid] - sAtLb[tid];
            nxtJ[tid] = Jb[(t + 1) * 16 + tid] + 0.5f;
            nxtH[tid] = Hb[(t + 1) * 16 + tid];
        }
        __syncthreads();

        float logdet = gj16<true>(MA, i, j);   // MA[:,16:32] = M^{-1}

        if (tid < 16) {
            float s = 0.f;
#pragma unroll
            for (int k = 0; k < 16; ++k) s = fmaf(MA[tid][16 + k], mvec[k], s);
            Mimv[tid] = s;                       // M^{-1} m
        }
        float g = 0.f;
#pragma unroll
        for (int k = 0; k < 16; ++k) g = fmaf(MA[i][16 + k], sAtL[k][j], g);
        Gm[i][j] = g;                            // G = M^{-1} A^tL
        __syncthreads();

        {
            float s = 0.f;
#pragma unroll
            for (int k = 0; k < 16; ++k) s = fmaf(mvec[k], Mimv[k], s);
            lz += 0.5f * s - 0.5f * logdet + trans_const;
        }
        scr1[(size_t)t * 256 + tid] = MA[i][16 + j];  // Pi
        scr2[(size_t)t * 256 + tid] = g;              // G
        if (tid < 16) scr3[(size_t)t * 16 + tid] = Mimv[tid];

        float pj = sLam[i][j];
#pragma unroll
        for (int k = 0; k < 16; ++k) pj = fmaf(-sAtL[k][i], Gm[k][j], pj);
        float newJ = pj + ((i == j) ? nxtJ[i] : 0.f);
        float newH = 0.f;
        if (tid < 16) {
            float s = sLb[tid];
#pragma unroll
            for (int k = 0; k < 16; ++k) s = fmaf(sAtL[k][tid], Mimv[k], s);
            newH = s + nxtH[tid];
        }
        PiG[i][j] = newJ;
        if (tid < 16) fh[tid] = newH;
        __syncthreads();
    }

    // ---- terminal: invert fJ_T ----
    MA[i][j]      = PiG[i][j];
    MA[i][j + 16] = (i == j) ? 1.f : 0.f;
    __syncthreads();
    float logdetT = gj16<true>(MA, i, j);
    if (tid < 16) {
        float s = 0.f;
#pragma unroll
        for (int k = 0; k < 16; ++k) s = fmaf(MA[tid][16 + k], fh[k], s);
        mT_s[tid] = s;                           // m_T = V_T fh_T
        nxtJ[tid] = Jb[(TT - 1) * 16 + tid] + 0.5f;
        nxtH[tid] = Hb[(TT - 1) * 16 + tid];
    }
    __syncthreads();
    float dotf = 0.f;
#pragma unroll
    for (int k = 0; k < 16; ++k) dotf = fmaf(fh[k], mT_s[k], dotf);
    float logZ = lz + init_const + 0.5f * dotf - 0.5f * logdetT;

    exxtO[(size_t)(TT - 1) * 256 + tid] = MA[i][16 + j] + mT_s[i] * mT_s[j];
    if (tid < 16) exO[(size_t)(TT - 1) * 16 + tid] = mT_s[tid];
    {
        float s = 0.f;
#pragma unroll
        for (int k = 0; k < 16; ++k)
            s += -0.5f * nxtJ[k] * (MA[k][16 + k] + mT_s[k] * mT_s[k]) + nxtH[k] * mT_s[k];
        klacc += s;
    }
    Vn[i][j] = MA[i][16 + j];
    if (tid < 16) mn[tid] = mT_s[tid];
    __syncthreads();

    // ======================= BACKWARD SMOOTHER =======================
    for (int t = TM1 - 1; t >= 0; --t) {
        PiG[i][j] = scr1[(size_t)t * 256 + tid];
        Gm[i][j]  = scr2[(size_t)t * 256 + tid];
        if (tid < 16) {
            Mimv[tid] = scr3[(size_t)t * 16 + tid];
            nxtJ[tid] = Jb[t * 16 + tid] + 0.5f;
            nxtH[tid] = Hb[t * 16 + tid];
        }
        __syncthreads();

        if (tid < 16) {
            float s = Mimv[tid];
#pragma unroll
            for (int k = 0; k < 16; ++k) s = fmaf(Gm[tid][k], mn[k], s);
            mt[tid] = s;                          // m_t
        }
        float w = 0.f;
#pragma unroll
        for (int k = 0; k < 16; ++k) w = fmaf(Gm[i][k], Vn[k][j], w);
        Wb[i][j] = w;                             // C_t = G V_n
        __syncthreads();

        float v = PiG[i][j];
#pragma unroll
        for (int k = 0; k < 16; ++k) v = fmaf(Wb[i][k], Gm[j][k], v);
        Vt[i][j] = v;
        exxtO [(size_t)t * 256 + tid] = v + mt[i] * mt[j];
        exxntO[(size_t)t * 256 + tid] = w + mt[i] * mn[j];
        if (tid < 16) {
            exO[(size_t)t * 16 + tid]  = mt[tid];
            scr3[(size_t)t * 16 + tid] = mt[tid];   // save m_t for sampling
        }
        __syncthreads();

        {
            float s = 0.f;
#pragma unroll
            for (int k = 0; k < 16; ++k)
                s += -0.5f * nxtJ[k] * (Vt[k][k] + mt[k] * mt[k]) + nxtH[k] * mt[k];
            klacc += s;
        }

        // K = V_t^{-1} C : GJ on [V_t | C]
        MA[i][j]      = Vt[i][j];
        MA[i][j + 16] = Wb[i][j];
        __syncthreads();
        gj16<false>(MA, i, j);                    // MA[:,16:] = K

        float cv = Vn[i][j];
#pragma unroll
        for (int k = 0; k < 16; ++k) cv = fmaf(-Wb[k][i], MA[k][16 + j], cv);
        if (i == j) cv += 1e-6f;                  // JITTER
        CH[i][j] = cv;
        scr1[(size_t)t * 256 + tid] = MA[j][16 + i];   // K^T
        __syncthreads();

        chol16(CH, i, j);                         // Ls
        scr2[(size_t)t * 256 + tid] = (j <= i) ? CH[i][j] : 0.f;

        Vn[i][j] = Vt[i][j];
        if (tid < 16) mn[tid] = mt[tid];
        __syncthreads();
    }

    // ======================= SAMPLING =======================
    CH[i][j] = Vn[i][j] + ((i == j) ? 1e-6f : 0.f);
    if (tid < 16) sE[tid] = epsb[tid];
    __syncthreads();
    chol16(CH, i, j);
    if (tid < 16) {
        float s = mn[tid];
        for (int k = 0; k <= tid; ++k) s = fmaf(CH[tid][k], sE[k], s);
        xc[tid] = s;
        zO[tid] = s;
    }
    __syncthreads();

    for (int t = 0; t < TM1; ++t) {
        PiG[i][j] = scr1[(size_t)t * 256 + tid];   // K^T
        Gm[i][j]  = scr2[(size_t)t * 256 + tid];   // Ls
        if (tid < 16) {
            mt[tid] = scr3[(size_t)t * 16 + tid];
            mn[tid] = (t < TM1 - 1) ? scr3[(size_t)(t + 1) * 16 + tid] : mT_s[tid];
            sE[tid] = epsb[(size_t)(t + 1) * 16 + tid];
        }
        __syncthreads();
        if (tid < 16) {
            float s = mn[tid];
#pragma unroll
            for (int k = 0; k < 16; ++k) s = fmaf(PiG[tid][k], xc[k] - mt[k], s);
            for (int k = 0; k <= tid; ++k) s = fmaf(Gm[tid][k], sE[k], s);
            xn[tid] = s;
        }
        __syncthreads();
        if (tid < 16) {
            xc[tid] = xn[tid];
            zO[(size_t)(t + 1) * 16 + tid] = xn[tid];
        }
        __syncthreads();
    }

    if (tid == 0) out[KL_OFF + b] = klacc - logZ;
}

// ---------------- launch ----------------
extern "C" void kernel_launch(void* const* d_in, const int* in_sizes, int n_in,
                              void* d_out, int out_size) {
    const float* Jr    = (const float*)d_in[0];
    const float* hr    = (const float*)d_in[1];
    const float* loc   = (const float*)d_in[2];
    const float* Tau_p = (const float*)d_in[3];
    const float* Lam_p = (const float*)d_in[4];
    const float* X     = (const float*)d_in[5];
    float* out = (float*)d_out;

    setup_kernel<<<1, 256>>>(loc, Tau_p, Lam_p, X);
    lds_main<<<BB, 256>>>(Jr, hr, out);
}

// round 11
// speedup vs baseline: 1.3460x; 1.3460x over previous
#include <cuda_runtime.h>
#include <cstdint>

#define TT   1000
#define TM1  999
#define BB   64

// ---------------- constants computed by setup kernel ----------------
__device__ float g_tau[256], g_lam[256], g_AtL[256], g_AtLA[256];
__device__ float g_tau_mu[16], g_AtLb[16], g_Lb[16];
__device__ float g_consts[2];          // [0]=trans_const, [1]=init_const
__device__ unsigned g_keys[BB][2];

// ---------------- scratch (device globals; no allocation) ----------------
__device__ float g_scr1[(size_t)BB * TM1 * 256]; // fwd: Pi   -> bwd: K^T
__device__ float g_scr2[(size_t)BB * TM1 * 256]; // fwd: G    -> bwd: Ls
__device__ float g_scr3[(size_t)BB * TT  * 16];  // fwd: Mim  -> bwd: m_t (slot TM1 = m_T)
__device__ float g_eps [(size_t)BB * TT  * 16];  // normal samples

// ---------------- Threefry-2x32 (20 rounds), JAX-compatible ----------------
__device__ __forceinline__ void tf2x32(unsigned k0, unsigned k1,
                                       unsigned x0, unsigned x1,
                                       unsigned &o0, unsigned &o1) {
    unsigned ks2 = k0 ^ k1 ^ 0x1BD11BDAu;
    x0 += k0; x1 += k1;
#define TFR(r) { x0 += x1; x1 = (x1 << (r)) | (x1 >> (32 - (r))); x1 ^= x0; }
    TFR(13) TFR(15) TFR(26) TFR(6)
    x0 += k1;  x1 += ks2 + 1u;
    TFR(17) TFR(29) TFR(16) TFR(24)
    x0 += ks2; x1 += k0 + 2u;
    TFR(13) TFR(15) TFR(26) TFR(6)
    x0 += k0;  x1 += k1 + 3u;
    TFR(17) TFR(29) TFR(16) TFR(24)
    x0 += k1;  x1 += ks2 + 4u;
    TFR(13) TFR(15) TFR(26) TFR(6)
    x0 += ks2; x1 += k0 + 5u;
#undef TFR
    o0 = x0; o1 = x1;
}

// ---- one in-place GJ pivot step on augmented [M(16) | R(16) | m(1)], double-buffered ----
// Left block becomes M^{-1} in place. One barrier per step. Returns the pivot.
__device__ __forceinline__ float gj_step(float (*C)[48], float (*N)[48],
                                         int k, int i, int j) {
    float piv  = C[k][k];
    float pinv = __fdividef(1.f, piv);
    float f    = C[i][k];
    float s0   = C[k][j]      * pinv;
    float s1   = C[k][j + 16] * pinv;
    float sm   = C[k][32]     * pinv;
    float a0   = C[i][j];
    float a1   = C[i][j + 16];
    float am   = C[i][32];
    float r0, r1, rm;
    if (i == k) {
        r0 = (j == k) ? pinv : s0;
        r1 = s1;
        rm = sm;
    } else {
        r0 = (j == k) ? (-f * pinv) : fmaf(-f, s0, a0);
        r1 = fmaf(-f, s1, a1);
        rm = fmaf(-f, sm, am);
    }
    N[i][j]      = r0;
    N[i][j + 16] = r1;
    if (j == 0) N[i][32] = rm;
    __syncthreads();
    return piv;
}

// ---- one Cholesky step (lower), double-buffered, one barrier per step ----
__device__ __forceinline__ void chol_step(float (*C)[48], float (*N)[48],
                                          int k, int i, int j) {
    float dk  = C[k][k];
    float inv = rsqrtf(dk);
    float cik = C[i][k], cjk = C[j][k], cij = C[i][j];
    float r;
    if (j < k)       r = cij;
    else if (j == k) r = (i >= k) ? cik * inv : cij;
    else             r = (i >= j) ? fmaf(-(cik * inv), cjk * inv, cij) : cij;
    N[i][j] = r;
    __syncthreads();
}

// ---------------- setup: shared model constants + batch keys ----------------
__device__ float logdet16_local(const float M[16][17]) {
    float a[16][16];
    for (int r = 0; r < 16; ++r)
        for (int c = 0; c < 16; ++c) a[r][c] = M[r][c];
    float ld = 0.f;
    for (int k = 0; k < 16; ++k) {
        float p = a[k][k];
        ld += logf(p);
        float pi_ = __fdiv_rn(1.f, p);
        for (int r = k + 1; r < 16; ++r) {
            float f = a[r][k] * pi_;
            for (int c = k + 1; c < 16; ++c) a[r][c] = fmaf(-f, a[k][c], a[r][c]);
        }
    }
    return ld;
}

__global__ void __launch_bounds__(256) setup_kernel(const float* __restrict__ loc,
                                                    const float* __restrict__ Tau_p,
                                                    const float* __restrict__ Lam_p,
                                                    const float* __restrict__ X) {
    __shared__ float sTau[16][17], sLamS[16][17], sA[16][17], sAtLs[16][17];
    __shared__ float sbv[16], slocv[16];
    int tid = threadIdx.x, i = tid >> 4, j = tid & 15;

    float t = 0.f, l = 0.f;
#pragma unroll
    for (int k = 0; k < 16; ++k) {
        t = fmaf(Tau_p[i * 16 + k], Tau_p[j * 16 + k], t);
        l = fmaf(Lam_p[i * 16 + k], Lam_p[j * 16 + k], l);
    }
    if (i == j) { t += 1e-8f; l += 1e-8f; }
    sTau[i][j] = t; sLamS[i][j] = l;
    sA[i][j]   = X[i * 17 + j];
    if (tid < 16) { sbv[tid] = X[tid * 17 + 16]; slocv[tid] = loc[tid]; }
    __syncthreads();

    float atl = 0.f;
#pragma unroll
    for (int k = 0; k < 16; ++k) atl = fmaf(sA[k][i], sLamS[k][j], atl);
    sAtLs[i][j] = atl;
    __syncthreads();

    float atla = 0.f;
#pragma unroll
    for (int k = 0; k < 16; ++k) atla = fmaf(sAtLs[i][k], sA[k][j], atla);

    g_tau[tid] = t; g_lam[tid] = l; g_AtL[tid] = atl; g_AtLA[tid] = atla;

    if (tid < 16) {
        float tm = 0.f, alb = 0.f, lb = 0.f;
#pragma unroll
        for (int k = 0; k < 16; ++k) {
            tm  = fmaf(sTau[tid][k],  slocv[k], tm);
            alb = fmaf(sAtLs[tid][k], sbv[k],   alb);
            lb  = fmaf(sLamS[tid][k], sbv[k],   lb);
        }
        g_tau_mu[tid] = tm; g_AtLb[tid] = alb; g_Lb[tid] = lb;
    }
    if (tid < BB) {
        unsigned o0, o1;
        tf2x32(0u, 42u, 0u, (unsigned)tid, o0, o1);
        g_keys[tid][0] = o0; g_keys[tid][1] = o1;
    }
    __syncthreads();
    if (tid == 0) {
        float ldl = logdet16_local(sLamS);
        float ldt = logdet16_local(sTau);
        float bLb = 0.f, ltm = 0.f;
        for (int k = 0; k < 16; ++k) {
            bLb = fmaf(sbv[k],   g_Lb[k],     bLb);
            ltm = fmaf(slocv[k], g_tau_mu[k], ltm);
        }
        g_consts[0] = -0.5f * bLb + 0.5f * ldl;  // trans_const
        g_consts[1] = -0.5f * ltm + 0.5f * ldt;  // init_const
    }
}

// ---------------- main: per-batch forward / backward / sample ----------------
__global__ void __launch_bounds__(256, 1) lds_main(const float* __restrict__ Jr,
                                                   const float* __restrict__ hr,
                                                   float* __restrict__ out) {
    const int b   = blockIdx.x;
    const int tid = threadIdx.x;
    const int i   = tid >> 4, j = tid & 15;

    const float trans_const = g_consts[0];
    const float init_const  = g_consts[1];

    const float* Jb = Jr + (size_t)b * TT * 16;
    const float* Hb = hr + (size_t)b * TT * 16;
    float* scr1 = g_scr1 + (size_t)b * TM1 * 256;
    float* scr2 = g_scr2 + (size_t)b * TM1 * 256;
    float* scr3 = g_scr3 + (size_t)b * TT * 16;
    float* epsb = g_eps  + (size_t)b * TT * 16;

    const size_t KL_OFF    = (size_t)BB * TT * 16;
    const size_t EXXT_OFF  = KL_OFF + BB;
    const size_t EX_OFF    = EXXT_OFF + (size_t)BB * TT * 256;
    const size_t EXXNT_OFF = EX_OFF + (size_t)BB * TT * 16;
    float* zO     = out + (size_t)b * TT * 16;
    float* exxtO  = out + EXXT_OFF + (size_t)b * TT * 256;
    float* exO    = out + EX_OFF + (size_t)b * TT * 16;
    float* exxntO = out + EXXNT_OFF + (size_t)b * TM1 * 256;

    __shared__ float B[2][16][48];               // GJ / chol ping-pong
    __shared__ float sAtL[16][17];
    __shared__ float Gm[16][17], Wb[16][17], Vn[16][17];
    __shared__ float fh[16], mv[16], nJ[16], nH[16];
    __shared__ float mt_s[16], mn[16], vtd[16], sAtLb[16];
    __shared__ float nJb[16], nHb[16];
    __shared__ float xs[2][16];

    // ---- epsilon generation (partitionable random_bits: lane0 ^ lane1) ----
    {
        unsigned k0 = g_keys[b][0], k1 = g_keys[b][1];
        for (int idx = tid; idx < TT * 16; idx += 256) {
            unsigned o0, o1;
            tf2x32(k0, k1, 0u, (unsigned)idx, o0, o1);
            unsigned bits = o0 ^ o1;
            float f = __uint_as_float((bits >> 9) | 0x3f800000u) - 1.0f;
            const float lo = -0.99999994f;
            float v = fmaxf(lo, f * 2.0f + lo);
            epsb[idx] = 1.4142135623730951f * erfinvf(v);
        }
    }

    // ---- constants + initial carry ----
    const float lam_r  = g_lam[tid];
    const float atla_r = g_AtLA[tid];
    sAtL[i][j] = g_AtL[tid];
    float fJ_r = g_tau[tid] + ((i == j) ? (Jb[i] + 0.5f) : 0.f);
    float lb_r = 0.f, jn_r = 0.f, hn_r = 0.f;
    if (tid < 16) {
        sAtLb[tid] = g_AtLb[tid];
        fh[tid]    = g_tau_mu[tid] + Hb[tid];
        lb_r = g_Lb[tid];
        jn_r = Jb[16 + tid];   // J/H at t=1, prefetched
        hn_r = Hb[16 + tid];
    }
    __syncthreads();

    float lz = 0.f, klacc = 0.f;

    // ======================= FORWARD FILTER (18 barriers/step) =======================
    for (int t = 0; t < TM1; ++t) {
        B[0][i][j]      = fJ_r + atla_r;         // M
        B[0][i][j + 16] = sAtL[i][j];            // -> G
        if (j == 0) B[0][i][32] = fh[i] - sAtLb[i];  // m -> Mim
        if (tid < 16) {
            mv[tid] = fh[tid] - sAtLb[tid];
            nJ[tid] = jn_r + 0.5f; nH[tid] = hn_r;
            int tn = t + 2;
            if (tn < TT) { jn_r = Jb[tn * 16 + tid]; hn_r = Hb[tn * 16 + tid]; }
        }
        __syncthreads();

        float pp1 = 1.f, pp2 = 1.f;
#pragma unroll
        for (int k = 0; k < 16; k += 2) {
            float pa = gj_step(B[0], B[1], k,     i, j);
            float pb = gj_step(B[1], B[0], k + 1, i, j);
            if (k < 8) { pp1 *= pa; pp1 *= pb; } else { pp2 *= pa; pp2 *= pb; }
        }
        // B[0] = [Pi | G | Mim]
        scr1[(size_t)t * 256 + tid] = B[0][i][j];
        scr2[(size_t)t * 256 + tid] = B[0][i][j + 16];
        if (tid < 16) scr3[(size_t)t * 16 + tid] = B[0][tid][32];

        float dot = 0.f;
#pragma unroll
        for (int k = 0; k < 16; ++k) dot = fmaf(mv[k], B[0][k][32], dot);
        lz += 0.5f * dot - 0.5f * (__logf(pp1) + __logf(pp2)) + trans_const;

        float nfJ = lam_r;
#pragma unroll
        for (int k = 0; k < 16; ++k) nfJ = fmaf(-sAtL[k][i], B[0][k][16 + j], nfJ);
        if (i == j) nfJ += nJ[i];
        if (tid < 16) {
            float s = lb_r;
#pragma unroll
            for (int k = 0; k < 16; ++k) s = fmaf(sAtL[k][tid], B[0][k][32], s);
            fh[tid] = s + nH[tid];               // old fh last read before GJ; safe
        }
        __syncthreads();
        fJ_r = nfJ;
    }

    // ---- terminal: invert fJ_T with fh as RHS ----
    B[0][i][j] = fJ_r;
    if (j == 0) B[0][i][32] = fh[i];
    __syncthreads();
    {
        float pp1 = 1.f, pp2 = 1.f;
#pragma unroll
        for (int k = 0; k < 16; k += 2) {
            float pa = gj_step(B[0], B[1], k,     i, j);
            float pb = gj_step(B[1], B[0], k + 1, i, j);
            if (k < 8) { pp1 *= pa; pp1 *= pb; } else { pp2 *= pa; pp2 *= pb; }
        }
        float dotT = 0.f;
#pragma unroll
        for (int k = 0; k < 16; ++k) dotT = fmaf(fh[k], B[0][k][32], dotT);
        lz += init_const + 0.5f * dotT - 0.5f * (__logf(pp1) + __logf(pp2));
    }
    float logZ = lz;
    if (tid < 16) mt_s[tid] = B[0][tid][32];     // m_T
    __syncthreads();
    exxtO[(size_t)(TT - 1) * 256 + tid] = B[0][i][j] + mt_s[i] * mt_s[j];
    if (tid < 16) {
        exO[(size_t)(TT - 1) * 16 + tid] = mt_s[tid];
        scr3[(size_t)TM1 * 16 + tid]     = mt_s[tid];
    }
    {
        float s = 0.f;
#pragma unroll
        for (int k = 0; k < 16; ++k)
            s += -0.5f * nJ[k] * (B[0][k][k] + mt_s[k] * mt_s[k]) + nH[k] * mt_s[k];
        klacc += s;
    }
    Vn[i][j] = B[0][i][j];
    if (tid < 16) mn[tid] = mt_s[tid];
    __syncthreads();

    // ======================= BACKWARD SMOOTHER (37 barriers/step) =======================
    float g_r  = scr2[(size_t)(TM1 - 1) * 256 + tid];
    float pi_r = scr1[(size_t)(TM1 - 1) * 256 + tid];
    float mim_r = 0.f, jb_r = 0.f, hb_r = 0.f;
    if (tid < 16) {
        mim_r = scr3[(size_t)(TM1 - 1) * 16 + tid];
        jb_r  = Jb[(TM1 - 1) * 16 + tid];
        hb_r  = Hb[(TM1 - 1) * 16 + tid];
    }
    for (int t = TM1 - 1; t >= 0; --t) {
        Gm[i][j] = g_r;
        float pi_c  = pi_r;
        float mim_c = mim_r;
        if (tid < 16) { nJb[tid] = jb_r + 0.5f; nHb[tid] = hb_r; }
        if (t > 0) {                              // prefetch t-1
            g_r  = scr2[(size_t)(t - 1) * 256 + tid];
            pi_r = scr1[(size_t)(t - 1) * 256 + tid];
            if (tid < 16) {
                mim_r = scr3[(size_t)(t - 1) * 16 + tid];
                jb_r  = Jb[(t - 1) * 16 + tid];
                hb_r  = Hb[(t - 1) * 16 + tid];
            }
        }
        __syncthreads();                          // b1

        float w = 0.f;
#pragma unroll
        for (int k = 0; k < 16; ++k) w = fmaf(Gm[i][k], Vn[k][j], w);
        Wb[i][j] = w;
        if (tid < 16) {
            float s = mim_c;
#pragma unroll
            for (int k = 0; k < 16; ++k) s = fmaf(Gm[tid][k], mn[k], s);
            mt_s[tid] = s;
        }
        __syncthreads();                          // b2

        float v = pi_c;
#pragma unroll
        for (int k = 0; k < 16; ++k) v = fmaf(Wb[i][k], Gm[j][k], v);
        exxtO [(size_t)t * 256 + tid] = v + mt_s[i] * mt_s[j];
        exxntO[(size_t)t * 256 + tid] = w + mt_s[i] * mn[j];
        if (tid < 16) {
            exO[(size_t)t * 16 + tid]  = mt_s[tid];
            scr3[(size_t)t * 16 + tid] = mt_s[tid];
        }
        B[0][i][j]      = v;                      // Vt
        B[0][i][j + 16] = w;                      // C
        if (j == 0) B[0][i][32] = 0.f;
        if (i == j) vtd[i] = v;
        __syncthreads();                          // b3

        {
            float s = 0.f;
#pragma unroll
            for (int k = 0; k < 16; ++k)
                s += -0.5f * nJb[k] * (vtd[k] + mt_s[k] * mt_s[k]) + nHb[k] * mt_s[k];
            klacc += s;
        }
#pragma unroll
        for (int k = 0; k < 16; k += 2) {         // K = Vt^{-1} C
            gj_step(B[0], B[1], k,     i, j);
            gj_step(B[1], B[0], k + 1, i, j);
        }
        float cv = Vn[i][j];
#pragma unroll
        for (int k = 0; k < 16; ++k) cv = fmaf(-Wb[k][i], B[0][k][16 + j], cv);
        if (i == j) cv += 1e-6f;                  // JITTER
        scr1[(size_t)t * 256 + tid] = B[0][j][16 + i];   // K^T
        B[0][i][j] = cv;                          // disjoint from cols 16..31 reads
        __syncthreads();                          // b4
#pragma unroll
        for (int k = 0; k < 16; k += 2) {         // Ls = chol(condV)
            chol_step(B[0], B[1], k,     i, j);
            chol_step(B[1], B[0], k + 1, i, j);
        }
        scr2[(size_t)t * 256 + tid] = (j <= i) ? B[0][i][j] : 0.f;
        Vn[i][j] = v;                             // next step reads after its b1
        if (tid < 16) mn[tid] = mt_s[tid];
    }
    __syncthreads();

    // ======================= SAMPLING (1 barrier/step) =======================
    B[0][i][j] = Vn[i][j] + ((i == j) ? 1e-6f : 0.f);
    __syncthreads();
#pragma unroll
    for (int k = 0; k < 16; k += 2) {
        chol_step(B[0], B[1], k,     i, j);
        chol_step(B[1], B[0], k + 1, i, j);
    }
    {
        float e0 = epsb[j];
        float v  = ((j <= i) ? B[0][i][j] : 0.f) * e0;
        v += __shfl_xor_sync(0xffffffffu, v, 1);
        v += __shfl_xor_sync(0xffffffffu, v, 2);
        v += __shfl_xor_sync(0xffffffffu, v, 4);
        v += __shfl_xor_sync(0xffffffffu, v, 8);
        if (j == 0) { float x = mn[i] + v; xs[0][i] = x; zO[i] = x; }
    }
    __syncthreads();

    float kt_r  = scr1[tid];
    float ls_r  = scr2[tid];
    float mtj_r = scr3[j];
    float mni_r = scr3[16 + i];
    float ej_r  = epsb[16 + j];
    for (int t = 0; t < TM1; ++t) {
        float kt = kt_r, ls = ls_r, mtj = mtj_r, mni = mni_r, ej = ej_r;
        if (t + 1 < TM1) {                        // prefetch t+1
            kt_r  = scr1[(size_t)(t + 1) * 256 + tid];
            ls_r  = scr2[(size_t)(t + 1) * 256 + tid];
            mtj_r = scr3[(size_t)(t + 1) * 16 + j];
            mni_r = scr3[(size_t)(t + 2) * 16 + i];
            ej_r  = epsb[(size_t)(t + 2) * 16 + j];
        }
        float v = kt * (xs[t & 1][j] - mtj) + ls * ej;
        v += __shfl_xor_sync(0xffffffffu, v, 1);
        v += __shfl_xor_sync(0xffffffffu, v, 2);
        v += __shfl_xor_sync(0xffffffffu, v, 4);
        v += __shfl_xor_sync(0xffffffffu, v, 8);
        if (j == 0) {
            float x = mni + v;
            xs[(t & 1) ^ 1][i] = x;
            zO[(size_t)(t + 1) * 16 + i] = x;
        }
        __syncthreads();
    }

    if (tid == 0) out[KL_OFF + b] = klacc - logZ;
}

// ---------------- launch ----------------
extern "C" void kernel_launch(void* const* d_in, const int* in_sizes, int n_in,
                              void* d_out, int out_size) {
    const float* Jr    = (const float*)d_in[0];
    const float* hr    = (const float*)d_in[1];
    const float* loc   = (const float*)d_in[2];
    const float* Tau_p = (const float*)d_in[3];
    const float* Lam_p = (const float*)d_in[4];
    const float* X     = (const float*)d_in[5];
    float* out = (float*)d_out;

    setup_kernel<<<1, 256>>>(loc, Tau_p, Lam_p, X);
    lds_main<<<BB, 256>>>(Jr, hr, out);
}